// round 3
// baseline (speedup 1.0000x reference)
#include <cuda_runtime.h>
#include <cuda_bf16.h>
#include <cstdint>

// Problem constants
constexpr int B_  = 4;
constexpr int S_  = 2048;
constexpr int D_  = 1024;       // D_IN == D_OUT
constexpr int NR  = B_ * S_;    // 8192 total rows

// Scratch (device globals: allocation-free contract)
__device__ float g_Q [NR * D_];                 // 32 MB
__device__ float g_K [NR * D_];                 // 32 MB
__device__ float g_V [NR * D_];                 // 32 MB
__device__ float g_SC[(size_t)B_ * S_ * S_];    // 64 MB

// ---------------------------------------------------------------------------
// Kernel 1: QKV projections.  C = X @ W   (X: [NR, D], W: [D, D] row-major)
// 128x128x8 tile, 8x8 per-thread micro-tile, 256 threads.
// blockIdx.z selects Wq/Wk/Wv -> g_Q/g_K/g_V.
// ---------------------------------------------------------------------------
__global__ void __launch_bounds__(256, 2) ca_proj_kernel(
    const float* __restrict__ X,
    const float* __restrict__ Wq,
    const float* __restrict__ Wk,
    const float* __restrict__ Wv)
{
    constexpr int BM = 128, BN = 128, BK = 8, TM = 8, TN = 8;
    const float* W = (blockIdx.z == 0) ? Wq : (blockIdx.z == 1) ? Wk : Wv;
    float*       C = (blockIdx.z == 0) ? g_Q : (blockIdx.z == 1) ? g_K : g_V;

    __shared__ float As[BK][BM];
    __shared__ float Bs[BK][BN];

    const int tid  = threadIdx.x;
    const int rowC = tid / (BN / TN);   // 0..15
    const int colC = tid % (BN / TN);   // 0..15
    const int mT   = blockIdx.y;        // M tile
    const int nT   = blockIdx.x;        // N tile

    const float* Aptr = X + (size_t)mT * BM * D_;
    const float* Bptr = W + nT * BN;

    // load indices
    const int aR = tid / 2;             // 0..127
    const int aC = (tid % 2) * 4;       // 0 or 4
    const int bR = tid / 32;            // 0..7
    const int bC = (tid % 32) * 4;      // 0..124

    float acc[TM][TN] = {};

    for (int k0 = 0; k0 < D_; k0 += BK) {
        float4 a4 = *reinterpret_cast<const float4*>(Aptr + (size_t)aR * D_ + k0 + aC);
        As[aC + 0][aR] = a4.x; As[aC + 1][aR] = a4.y;
        As[aC + 2][aR] = a4.z; As[aC + 3][aR] = a4.w;
        float4 b4 = *reinterpret_cast<const float4*>(Bptr + (size_t)(k0 + bR) * D_ + bC);
        *reinterpret_cast<float4*>(&Bs[bR][bC]) = b4;
        __syncthreads();

        #pragma unroll
        for (int k = 0; k < BK; k++) {
            float ra[TM], rb[TN];
            #pragma unroll
            for (int i = 0; i < TM; i++) ra[i] = As[k][rowC * TM + i];
            #pragma unroll
            for (int j = 0; j < TN; j++) rb[j] = Bs[k][colC * TN + j];
            #pragma unroll
            for (int i = 0; i < TM; i++)
                #pragma unroll
                for (int j = 0; j < TN; j++)
                    acc[i][j] += ra[i] * rb[j];
        }
        __syncthreads();
    }

    float* Cptr = C + (size_t)(mT * BM) * D_ + nT * BN;
    #pragma unroll
    for (int i = 0; i < TM; i++) {
        #pragma unroll
        for (int j = 0; j < TN; j += 4) {
            float4 v = make_float4(acc[i][j], acc[i][j+1], acc[i][j+2], acc[i][j+3]);
            *reinterpret_cast<float4*>(Cptr + (size_t)(rowC*TM + i) * D_ + colC*TN + j) = v;
        }
    }
}

// ---------------------------------------------------------------------------
// Kernel 2: scores = (Q @ K^T) * scale   per batch.  NT GEMM, causal-skip.
// Only lower-triangular (kt <= qt) tiles are computed. Entries with k > q in
// diagonal blocks are garbage — softmax never reads them.
// ---------------------------------------------------------------------------
__global__ void __launch_bounds__(256, 2) ca_scores_kernel()
{
    constexpr int BM = 128, BN = 128, BK = 8, TM = 8, TN = 8;
    const int kt = blockIdx.x, qt = blockIdx.y, b = blockIdx.z;
    if (kt > qt) return;

    const float* Qp = g_Q + (size_t)b * S_ * D_ + (size_t)qt * BM * D_;
    const float* Kp = g_K + (size_t)b * S_ * D_ + (size_t)kt * BN * D_;
    float*       Cp = g_SC + (size_t)b * S_ * S_ + (size_t)(qt * BM) * S_ + kt * BN;

    __shared__ float As[BK][BM];
    __shared__ float Bs[BK][BN];

    const int tid  = threadIdx.x;
    const int rowC = tid / (BN / TN);
    const int colC = tid % (BN / TN);
    const int lR = tid / 2;            // 0..127
    const int lC = (tid % 2) * 4;      // 0 or 4

    float acc[TM][TN] = {};

    for (int k0 = 0; k0 < D_; k0 += BK) {
        float4 a4 = *reinterpret_cast<const float4*>(Qp + (size_t)lR * D_ + k0 + lC);
        float4 b4 = *reinterpret_cast<const float4*>(Kp + (size_t)lR * D_ + k0 + lC);
        As[lC + 0][lR] = a4.x; As[lC + 1][lR] = a4.y;
        As[lC + 2][lR] = a4.z; As[lC + 3][lR] = a4.w;
        Bs[lC + 0][lR] = b4.x; Bs[lC + 1][lR] = b4.y;
        Bs[lC + 2][lR] = b4.z; Bs[lC + 3][lR] = b4.w;
        __syncthreads();

        #pragma unroll
        for (int k = 0; k < BK; k++) {
            float ra[TM], rb[TN];
            #pragma unroll
            for (int i = 0; i < TM; i++) ra[i] = As[k][rowC * TM + i];
            #pragma unroll
            for (int j = 0; j < TN; j++) rb[j] = Bs[k][colC * TN + j];
            #pragma unroll
            for (int i = 0; i < TM; i++)
                #pragma unroll
                for (int j = 0; j < TN; j++)
                    acc[i][j] += ra[i] * rb[j];
        }
        __syncthreads();
    }

    const float scale = 0.03125f;   // 1/sqrt(1024)
    #pragma unroll
    for (int i = 0; i < TM; i++) {
        #pragma unroll
        for (int j = 0; j < TN; j += 4) {
            float4 v = make_float4(acc[i][j]*scale, acc[i][j+1]*scale,
                                   acc[i][j+2]*scale, acc[i][j+3]*scale);
            *reinterpret_cast<float4*>(Cp + (size_t)(rowC*TM + i) * S_ + colC*TN + j) = v;
        }
    }
}

// ---------------------------------------------------------------------------
// Kernel 3: causal row softmax in-place on g_SC. One block per row.
// Row q reads [0, q], writes normalized probs there, zeros [q+1, S).
// ---------------------------------------------------------------------------
__global__ void __launch_bounds__(256) ca_softmax_kernel()
{
    __shared__ float buf[S_];
    __shared__ float red[256];

    const int row = blockIdx.x;          // 0..NR-1
    const int b   = row >> 11;
    const int q   = row & (S_ - 1);
    float* sc = g_SC + (size_t)b * S_ * S_ + (size_t)q * S_;
    const int len = q + 1;
    const int tid = threadIdx.x;

    float m = -3.4e38f;
    for (int i = tid; i < len; i += 256) {
        float v = sc[i];
        buf[i] = v;
        m = fmaxf(m, v);
    }
    red[tid] = m;
    __syncthreads();
    #pragma unroll
    for (int s = 128; s > 0; s >>= 1) {
        if (tid < s) red[tid] = fmaxf(red[tid], red[tid + s]);
        __syncthreads();
    }
    m = red[0];
    __syncthreads();

    float sum = 0.f;
    for (int i = tid; i < len; i += 256) {
        float e = __expf(buf[i] - m);
        buf[i] = e;
        sum += e;
    }
    red[tid] = sum;
    __syncthreads();
    #pragma unroll
    for (int s = 128; s > 0; s >>= 1) {
        if (tid < s) red[tid] += red[tid + s];
        __syncthreads();
    }
    const float inv = 1.0f / red[0];

    for (int i = tid; i < len; i += 256) sc[i] = buf[i] * inv;
    for (int i = len + tid; i < S_; i += 256) sc[i] = 0.f;
}

// ---------------------------------------------------------------------------
// Kernel 4: O = attn @ V  per batch. NN GEMM, k-loop bounded by causality.
// A = g_SC (row stride S_), B = g_V (row stride D_), C = out (row stride D_).
// ---------------------------------------------------------------------------
__global__ void __launch_bounds__(256, 2) ca_pv_kernel(float* __restrict__ out)
{
    constexpr int BM = 128, BN = 128, BK = 8, TM = 8, TN = 8;
    const int nT = blockIdx.x, qT = blockIdx.y, b = blockIdx.z;

    const float* Ap = g_SC + (size_t)b * S_ * S_ + (size_t)(qT * BM) * S_;
    const float* Bp = g_V  + (size_t)b * S_ * D_ + nT * BN;
    float*       Cp = out  + (size_t)b * S_ * D_ + (size_t)(qT * BM) * D_ + nT * BN;

    const int kLim = min(S_, qT * BM + BM);   // attn row q is zero beyond block diag

    __shared__ float As[BK][BM];
    __shared__ float Bs[BK][BN];

    const int tid  = threadIdx.x;
    const int rowC = tid / (BN / TN);
    const int colC = tid % (BN / TN);
    const int aR = tid / 2;
    const int aC = (tid % 2) * 4;
    const int bR = tid / 32;
    const int bC = (tid % 32) * 4;

    float acc[TM][TN] = {};

    for (int k0 = 0; k0 < kLim; k0 += BK) {
        float4 a4 = *reinterpret_cast<const float4*>(Ap + (size_t)aR * S_ + k0 + aC);
        As[aC + 0][aR] = a4.x; As[aC + 1][aR] = a4.y;
        As[aC + 2][aR] = a4.z; As[aC + 3][aR] = a4.w;
        float4 b4 = *reinterpret_cast<const float4*>(Bp + (size_t)(k0 + bR) * D_ + bC);
        *reinterpret_cast<float4*>(&Bs[bR][bC]) = b4;
        __syncthreads();

        #pragma unroll
        for (int k = 0; k < BK; k++) {
            float ra[TM], rb[TN];
            #pragma unroll
            for (int i = 0; i < TM; i++) ra[i] = As[k][rowC * TM + i];
            #pragma unroll
            for (int j = 0; j < TN; j++) rb[j] = Bs[k][colC * TN + j];
            #pragma unroll
            for (int i = 0; i < TM; i++)
                #pragma unroll
                for (int j = 0; j < TN; j++)
                    acc[i][j] += ra[i] * rb[j];
        }
        __syncthreads();
    }

    #pragma unroll
    for (int i = 0; i < TM; i++) {
        #pragma unroll
        for (int j = 0; j < TN; j += 4) {
            float4 v = make_float4(acc[i][j], acc[i][j+1], acc[i][j+2], acc[i][j+3]);
            *reinterpret_cast<float4*>(Cp + (size_t)(rowC*TM + i) * D_ + colC*TN + j) = v;
        }
    }
}

// ---------------------------------------------------------------------------
extern "C" void kernel_launch(void* const* d_in, const int* in_sizes, int n_in,
                              void* d_out, int out_size)
{
    const float* x  = (const float*)d_in[0];
    const float* Wq = (const float*)d_in[1];
    const float* Wk = (const float*)d_in[2];
    const float* Wv = (const float*)d_in[3];
    float* out = (float*)d_out;

    // 1) QKV projections: grid (N tiles, M tiles, 3)
    dim3 g1(D_ / 128, NR / 128, 3);
    ca_proj_kernel<<<g1, 256>>>(x, Wq, Wk, Wv);

    // 2) Scores (causal lower-tri tiles only)
    dim3 g2(S_ / 128, S_ / 128, B_);
    ca_scores_kernel<<<g2, 256>>>();

    // 3) Row softmax
    ca_softmax_kernel<<<NR, 256>>>();

    // 4) O = attn @ V
    dim3 g3(D_ / 128, S_ / 128, B_);
    ca_pv_kernel<<<g3, 256>>>(out);
}

// round 5
// speedup vs baseline: 1.3053x; 1.3053x over previous
#include <cuda_runtime.h>
#include <cuda_bf16.h>
#include <cstdint>

// Problem constants
constexpr int B_  = 4;
constexpr int S_  = 2048;
constexpr int D_  = 1024;
constexpr int NR  = B_ * S_;

// Scratch (device globals: allocation-free contract)
__device__ float g_Q [NR * D_];
__device__ float g_K [NR * D_];
__device__ float g_V [NR * D_];
__device__ float g_SC[(size_t)B_ * S_ * S_];

// ---------------------------------------------------------------------------
// SMEM layout: 4 x 16KB bf16 tiles [128 rows x 64 cols], SW128 swizzled
// ---------------------------------------------------------------------------
constexpr int SM_AH = 0;
constexpr int SM_AL = 16384;
constexpr int SM_BH = 32768;
constexpr int SM_BL = 49152;
constexpr int SMEM_TOTAL = 65536;

__device__ __forceinline__ uint32_t swz(uint32_t off) {
    return off ^ ((off >> 3) & 0x70);
}
__device__ __forceinline__ uint32_t smem_u32(const void* p) {
    uint32_t a;
    asm("{ .reg .u64 t; cvta.to.shared.u64 t, %1; cvt.u32.u64 %0, t; }" : "=r"(a) : "l"(p));
    return a;
}
__device__ __forceinline__ uint32_t pkb(__nv_bfloat16 a, __nv_bfloat16 b) {
    uint16_t x = __bfloat16_as_ushort(a), y = __bfloat16_as_ushort(b);
    return (uint32_t)x | ((uint32_t)y << 16);
}

// ldmatrix x4 (arch-agnostic, sm_75+)
#define LDSM_X4(r0, r1, r2, r3, addr) \
    asm volatile("ldmatrix.sync.aligned.m8n8.x4.shared.b16 {%0,%1,%2,%3}, [%4];" \
        : "=r"(r0), "=r"(r1), "=r"(r2), "=r"(r3) : "r"(addr))

// mma.sync bf16 (arch-agnostic, sm_80+) -> HMMA in SASS
#define MMA_BF16(c, a, b0, b1) \
    asm volatile("mma.sync.aligned.m16n8k16.row.col.f32.bf16.bf16.f32 " \
        "{%0,%1,%2,%3}, {%4,%5,%6,%7}, {%8,%9}, {%0,%1,%2,%3};" \
        : "+f"((c)[0]), "+f"((c)[1]), "+f"((c)[2]), "+f"((c)[3]) \
        : "r"((a)[0]), "r"((a)[1]), "r"((a)[2]), "r"((a)[3]), "r"(b0), "r"(b1))

// ---------------------------------------------------------------------------
// fp32 [128 x 64] tile (K-major source, row stride ld) -> hi/lo bf16 SW128 tiles
// ---------------------------------------------------------------------------
__device__ __forceinline__ void conv_direct(const float* __restrict__ src, int ld,
                                            char* smem, int offH, int offL, int tid) {
    #pragma unroll
    for (int it = 0; it < 4; it++) {
        int idx = it * 256 + tid;
        int r = idx >> 3, c8 = (idx & 7) * 8;
        const float* p = src + (size_t)r * ld + c8;
        float4 f0 = *(const float4*)p;
        float4 f1 = *(const float4*)(p + 4);
        float f[8] = {f0.x, f0.y, f0.z, f0.w, f1.x, f1.y, f1.z, f1.w};
        uint32_t hw[4], lw[4];
        #pragma unroll
        for (int j = 0; j < 4; j++) {
            __nv_bfloat16 ah = __float2bfloat16(f[2*j]);
            __nv_bfloat16 bh = __float2bfloat16(f[2*j+1]);
            hw[j] = pkb(ah, bh);
            lw[j] = pkb(__float2bfloat16(f[2*j]   - __bfloat162float(ah)),
                        __float2bfloat16(f[2*j+1] - __bfloat162float(bh)));
        }
        uint32_t sw = swz((uint32_t)r * 128u + (uint32_t)c8 * 2u);
        *(uint4*)(smem + offH + sw) = make_uint4(hw[0], hw[1], hw[2], hw[3]);
        *(uint4*)(smem + offL + sw) = make_uint4(lw[0], lw[1], lw[2], lw[3]);
    }
}

// fp32 [64 x 128] source (row=k, col=n, row stride ld) -> transposed [n][k] hi/lo tiles
__device__ __forceinline__ void conv_trans(const float* __restrict__ src, int ld,
                                           char* smem, int offH, int offL, int tid) {
    #pragma unroll
    for (int it = 0; it < 2; it++) {
        int idx = it * 256 + tid;          // 0..511
        int k2 = idx >> 4;                 // 0..31 -> k = 2*k2
        int n8 = (idx & 15) * 8;           // 0..120
        const float* p0 = src + (size_t)(2 * k2) * ld + n8;
        const float* p1 = p0 + ld;
        float4 x0 = *(const float4*)p0;
        float4 x1 = *(const float4*)(p0 + 4);
        float4 y0 = *(const float4*)p1;
        float4 y1 = *(const float4*)(p1 + 4);
        float fa[8] = {x0.x, x0.y, x0.z, x0.w, x1.x, x1.y, x1.z, x1.w};
        float fb[8] = {y0.x, y0.y, y0.z, y0.w, y1.x, y1.y, y1.z, y1.w};
        #pragma unroll
        for (int j = 0; j < 8; j++) {
            __nv_bfloat16 ah = __float2bfloat16(fa[j]);
            __nv_bfloat16 bh = __float2bfloat16(fb[j]);
            uint32_t hw = pkb(ah, bh);
            uint32_t lw = pkb(__float2bfloat16(fa[j] - __bfloat162float(ah)),
                              __float2bfloat16(fb[j] - __bfloat162float(bh)));
            uint32_t sw = swz((uint32_t)(n8 + j) * 128u + (uint32_t)k2 * 4u);
            *(uint32_t*)(smem + offH + sw) = hw;
            *(uint32_t*)(smem + offL + sw) = lw;
        }
    }
}

// ---------------------------------------------------------------------------
// Unified mma.sync GEMM kernel. 128x128 tile, K-chunk 64, split-bf16 (3 passes).
// 8 warps, 4(m) x 2(n) warp grid, each warp 32x64 via m16n8k16 tiles.
// MODE 0: proj   C = X @ W       (B transposed on load)
// MODE 1: scores C = Q @ K^T * s (B direct K-major, causal tile skip)
// MODE 2: pv     C = P @ V       (B transposed, K bounded by causality)
// ---------------------------------------------------------------------------
template<int MODE>
__global__ void __launch_bounds__(256) ca_mma_kernel(
    const float* __restrict__ X, const float* __restrict__ Wq,
    const float* __restrict__ Wk, const float* __restrict__ Wv,
    float* __restrict__ Out)
{
    extern __shared__ char smem[];

    const float* Ap; const float* Bt; float* Cp;
    int lda, ldb, ldc, nchunks;
    float scale = 1.0f;

    if constexpr (MODE == 0) {
        int nT = blockIdx.x, mT = blockIdx.y, z = blockIdx.z;
        const float* W = (z == 0) ? Wq : (z == 1) ? Wk : Wv;
        Ap = X + (size_t)mT * 128 * D_;                     lda = D_;
        Bt = W + nT * 128;                                  ldb = D_;
        Cp = ((z == 0) ? g_Q : (z == 1) ? g_K : g_V)
             + (size_t)mT * 128 * D_ + nT * 128;            ldc = D_;
        nchunks = D_ / 64;
    } else if constexpr (MODE == 1) {
        int kt = blockIdx.x, qt = blockIdx.y, b = blockIdx.z;
        if (kt > qt) return;
        Ap = g_Q + (size_t)b * S_ * D_ + (size_t)qt * 128 * D_;  lda = D_;
        Bt = g_K + (size_t)b * S_ * D_ + (size_t)kt * 128 * D_;  ldb = D_;
        Cp = g_SC + (size_t)b * S_ * S_ + (size_t)qt * 128 * S_ + kt * 128;
        ldc = S_;
        nchunks = D_ / 64;
        scale = 0.03125f;   // 1/sqrt(1024)
    } else {
        int nT = blockIdx.x, qT = blockIdx.y, b = blockIdx.z;
        Ap = g_SC + (size_t)b * S_ * S_ + (size_t)qT * 128 * S_;  lda = S_;
        Bt = g_V + (size_t)b * S_ * D_ + nT * 128;                ldb = D_;
        Cp = Out + (size_t)b * S_ * D_ + (size_t)qT * 128 * D_ + nT * 128;
        ldc = D_;
        nchunks = (qT + 1) * 2;   // causal: K limit = (qT+1)*128
    }

    const uint32_t sb = smem_u32(smem);
    const int tid  = threadIdx.x;
    const int wid  = tid >> 5, lane = tid & 31;
    const int wm   = wid >> 1;          // 0..3  (rows wm*32 .. +32)
    const int wn   = wid & 1;           // 0..1  (cols wn*64 .. +64)

    // ldmatrix per-thread addressing: lane&15 -> submatrix row, (lane>>4)*8 -> k offset
    const int lrow  = lane & 15;
    const int lkofs = (lane >> 4) * 8;  // elements

    float acc[2][8][4] = {};

    for (int ch = 0; ch < nchunks; ch++) {
        const int k0 = ch * 64;

        if (ch > 0) __syncthreads();   // buffer reuse: wait for previous MMA reads
        conv_direct(Ap + k0, lda, smem, SM_AH, SM_AL, tid);
        if constexpr (MODE == 1)
            conv_direct(Bt + k0, ldb, smem, SM_BH, SM_BL, tid);
        else
            conv_trans(Bt + (size_t)k0 * ldb, ldb, smem, SM_BH, SM_BL, tid);
        __syncthreads();

        #pragma unroll
        for (int ks = 0; ks < 4; ks++) {
            const uint32_t colb = (uint32_t)(ks * 16 + lkofs) * 2u;

            // A fragments (hi & lo), 2 m-tiles each
            uint32_t ah[2][4], al[2][4];
            #pragma unroll
            for (int mt = 0; mt < 2; mt++) {
                uint32_t ro = (uint32_t)(wm * 32 + mt * 16 + lrow) * 128u;
                uint32_t sw = swz(ro + colb);
                LDSM_X4(ah[mt][0], ah[mt][1], ah[mt][2], ah[mt][3], sb + SM_AH + sw);
                LDSM_X4(al[mt][0], al[mt][1], al[mt][2], al[mt][3], sb + SM_AL + sw);
            }

            // B hi fragments: 4 x4 loads covering n16 each
            uint32_t bb[4][4];
            #pragma unroll
            for (int nt2 = 0; nt2 < 4; nt2++) {
                uint32_t ro = (uint32_t)(wn * 64 + nt2 * 16 + lrow) * 128u;
                LDSM_X4(bb[nt2][0], bb[nt2][1], bb[nt2][2], bb[nt2][3],
                        sb + SM_BH + swz(ro + colb));
            }
            // pass 1: Ah * Bh ; pass 2: Al * Bh
            #pragma unroll
            for (int mt = 0; mt < 2; mt++)
                #pragma unroll
                for (int nt = 0; nt < 8; nt++) {
                    const int nt2 = nt >> 1, pr = nt & 1;
                    MMA_BF16(acc[mt][nt], ah[mt], bb[nt2][pr], bb[nt2][pr + 2]);
                }
            #pragma unroll
            for (int mt = 0; mt < 2; mt++)
                #pragma unroll
                for (int nt = 0; nt < 8; nt++) {
                    const int nt2 = nt >> 1, pr = nt & 1;
                    MMA_BF16(acc[mt][nt], al[mt], bb[nt2][pr], bb[nt2][pr + 2]);
                }
            // B lo fragments overwrite bb; pass 3: Ah * Bl
            #pragma unroll
            for (int nt2 = 0; nt2 < 4; nt2++) {
                uint32_t ro = (uint32_t)(wn * 64 + nt2 * 16 + lrow) * 128u;
                LDSM_X4(bb[nt2][0], bb[nt2][1], bb[nt2][2], bb[nt2][3],
                        sb + SM_BL + swz(ro + colb));
            }
            #pragma unroll
            for (int mt = 0; mt < 2; mt++)
                #pragma unroll
                for (int nt = 0; nt < 8; nt++) {
                    const int nt2 = nt >> 1, pr = nt & 1;
                    MMA_BF16(acc[mt][nt], ah[mt], bb[nt2][pr], bb[nt2][pr + 2]);
                }
        }
    }

    // Epilogue: c0,c1 -> (row, col..col+1); c2,c3 -> (row+8, same cols)
    const int erow = wm * 32 + (lane >> 2);
    const int ecol = wn * 64 + (lane & 3) * 2;
    #pragma unroll
    for (int mt = 0; mt < 2; mt++) {
        #pragma unroll
        for (int nt = 0; nt < 8; nt++) {
            float* d0 = Cp + (size_t)(erow + mt * 16)     * ldc + ecol + nt * 8;
            float* d1 = Cp + (size_t)(erow + mt * 16 + 8) * ldc + ecol + nt * 8;
            *(float2*)d0 = make_float2(acc[mt][nt][0] * scale, acc[mt][nt][1] * scale);
            *(float2*)d1 = make_float2(acc[mt][nt][2] * scale, acc[mt][nt][3] * scale);
        }
    }
}

// ---------------------------------------------------------------------------
// Causal row softmax, in-place on g_SC
// ---------------------------------------------------------------------------
__global__ void __launch_bounds__(256) ca_softmax_kernel()
{
    __shared__ float buf[S_];
    __shared__ float red[256];

    const int row = blockIdx.x;
    const int b   = row >> 11;
    const int q   = row & (S_ - 1);
    float* sc = g_SC + (size_t)b * S_ * S_ + (size_t)q * S_;
    const int len = q + 1;
    const int tid = threadIdx.x;

    float m = -3.4e38f;
    for (int i = tid; i < len; i += 256) {
        float v = sc[i];
        buf[i] = v;
        m = fmaxf(m, v);
    }
    red[tid] = m;
    __syncthreads();
    #pragma unroll
    for (int s = 128; s > 0; s >>= 1) {
        if (tid < s) red[tid] = fmaxf(red[tid], red[tid + s]);
        __syncthreads();
    }
    m = red[0];
    __syncthreads();

    float sum = 0.f;
    for (int i = tid; i < len; i += 256) {
        float e = __expf(buf[i] - m);
        buf[i] = e;
        sum += e;
    }
    red[tid] = sum;
    __syncthreads();
    #pragma unroll
    for (int s = 128; s > 0; s >>= 1) {
        if (tid < s) red[tid] += red[tid + s];
        __syncthreads();
    }
    const float inv = 1.0f / red[0];

    for (int i = tid; i < len; i += 256) sc[i] = buf[i] * inv;
    for (int i = len + tid; i < S_; i += 256) sc[i] = 0.f;
}

// ---------------------------------------------------------------------------
extern "C" void kernel_launch(void* const* d_in, const int* in_sizes, int n_in,
                              void* d_out, int out_size)
{
    const float* x  = (const float*)d_in[0];
    const float* Wq = (const float*)d_in[1];
    const float* Wk = (const float*)d_in[2];
    const float* Wv = (const float*)d_in[3];
    float* out = (float*)d_out;

    cudaFuncSetAttribute(ca_mma_kernel<0>, cudaFuncAttributeMaxDynamicSharedMemorySize, SMEM_TOTAL);
    cudaFuncSetAttribute(ca_mma_kernel<1>, cudaFuncAttributeMaxDynamicSharedMemorySize, SMEM_TOTAL);
    cudaFuncSetAttribute(ca_mma_kernel<2>, cudaFuncAttributeMaxDynamicSharedMemorySize, SMEM_TOTAL);

    // 1) QKV projections
    ca_mma_kernel<0><<<dim3(D_ / 128, NR / 128, 3), 256, SMEM_TOTAL>>>(x, Wq, Wk, Wv, out);
    // 2) Scores (causal lower-tri tiles only)
    ca_mma_kernel<1><<<dim3(S_ / 128, S_ / 128, B_), 256, SMEM_TOTAL>>>(x, Wq, Wk, Wv, out);
    // 3) Row softmax
    ca_softmax_kernel<<<NR, 256>>>();
    // 4) O = attn @ V
    ca_mma_kernel<2><<<dim3(D_ / 128, S_ / 128, B_), 256, SMEM_TOTAL>>>(x, Wq, Wk, Wv, out);
}

// round 7
// speedup vs baseline: 2.9484x; 2.2588x over previous
#include <cuda_runtime.h>
#include <cuda_bf16.h>
#include <cstdint>

// Problem constants
constexpr int B_  = 4;
constexpr int S_  = 2048;
constexpr int D_  = 1024;
constexpr int NR  = B_ * S_;

// ---------------------------------------------------------------------------
// Persistent bf16 hi/lo operand arrays + fp32 scores (device globals)
// ---------------------------------------------------------------------------
__device__ __nv_bfloat16 g_Xh [NR * D_];
__device__ __nv_bfloat16 g_Xl [NR * D_];
__device__ __nv_bfloat16 g_Wth[3 * D_ * D_];     // W^T, [z][e][d]
__device__ __nv_bfloat16 g_Wtl[3 * D_ * D_];
__device__ __nv_bfloat16 g_Qh [NR * D_];
__device__ __nv_bfloat16 g_Ql [NR * D_];
__device__ __nv_bfloat16 g_Kh [NR * D_];
__device__ __nv_bfloat16 g_Kl [NR * D_];
__device__ __nv_bfloat16 g_Vh [NR * D_];         // row-major [b*s][d]
__device__ __nv_bfloat16 g_Vl [NR * D_];
__device__ __nv_bfloat16 g_Vth[NR * D_];         // V^T, [b][d][s]
__device__ __nv_bfloat16 g_Vtl[NR * D_];
__device__ float         g_SC [(size_t)B_ * S_ * S_];
__device__ __nv_bfloat16 g_Ph [(size_t)B_ * S_ * S_];
__device__ __nv_bfloat16 g_Pl [(size_t)B_ * S_ * S_];

// ---------------------------------------------------------------------------
// Helpers
// ---------------------------------------------------------------------------
__device__ __forceinline__ uint32_t swz(uint32_t off) {
    return off ^ ((off >> 3) & 0x70);
}
__device__ __forceinline__ uint32_t smem_u32(const void* p) {
    uint32_t a;
    asm("{ .reg .u64 t; cvta.to.shared.u64 t, %1; cvt.u32.u64 %0, t; }" : "=r"(a) : "l"(p));
    return a;
}
__device__ __forceinline__ void split2(float v, __nv_bfloat16& h, __nv_bfloat16& l) {
    h = __float2bfloat16(v);
    l = __float2bfloat16(v - __bfloat162float(h));
}

#define LDSM_X4(r0, r1, r2, r3, addr) \
    asm volatile("ldmatrix.sync.aligned.m8n8.x4.shared.b16 {%0,%1,%2,%3}, [%4];" \
        : "=r"(r0), "=r"(r1), "=r"(r2), "=r"(r3) : "r"(addr))

#define MMA_BF16(c, a, b0, b1) \
    asm volatile("mma.sync.aligned.m16n8k16.row.col.f32.bf16.bf16.f32 " \
        "{%0,%1,%2,%3}, {%4,%5,%6,%7}, {%8,%9}, {%0,%1,%2,%3};" \
        : "+f"((c)[0]), "+f"((c)[1]), "+f"((c)[2]), "+f"((c)[3]) \
        : "r"((a)[0]), "r"((a)[1]), "r"((a)[2]), "r"((a)[3]), "r"(b0), "r"(b1))

__device__ __forceinline__ void cp16(uint32_t dst, const void* src) {
    asm volatile("cp.async.cg.shared.global [%0], [%1], 16;" :: "r"(dst), "l"(src));
}
#define CP_COMMIT() asm volatile("cp.async.commit_group;" ::: "memory")
#define CP_WAIT(n)  asm volatile("cp.async.wait_group %0;" :: "n"(n) : "memory")

// ---------------------------------------------------------------------------
// Conversion kernels (run once, memory-bound)
// ---------------------------------------------------------------------------
__global__ void __launch_bounds__(256) ca_split_x(const float* __restrict__ X)
{
    int idx = (blockIdx.x * 256 + threadIdx.x) * 4;
    if (idx >= NR * D_) return;
    float4 f = *(const float4*)(X + idx);
    __nv_bfloat16 h[4], l[4];
    split2(f.x, h[0], l[0]); split2(f.y, h[1], l[1]);
    split2(f.z, h[2], l[2]); split2(f.w, h[3], l[3]);
    *(uint2*)(g_Xh + idx) = *(uint2*)h;
    *(uint2*)(g_Xl + idx) = *(uint2*)l;
}

// W [d][e] fp32 -> W^T [e][d] bf16 hi/lo, 32x32 smem tiles
__global__ void __launch_bounds__(256) ca_tsplit_w(
    const float* __restrict__ Wq, const float* __restrict__ Wk,
    const float* __restrict__ Wv)
{
    __shared__ float tf[32][33];
    const int z = blockIdx.z;
    const float* W = (z == 0) ? Wq : (z == 1) ? Wk : Wv;
    const int dt = blockIdx.y * 32, et = blockIdx.x * 32;
    const int tx = threadIdx.x & 31, ty = threadIdx.x >> 5;   // ty 0..7
    #pragma unroll
    for (int i = 0; i < 32; i += 8)
        tf[ty + i][tx] = W[(size_t)(dt + ty + i) * D_ + et + tx];
    __syncthreads();
    __nv_bfloat16* Oh = g_Wth + (size_t)z * D_ * D_;
    __nv_bfloat16* Ol = g_Wtl + (size_t)z * D_ * D_;
    #pragma unroll
    for (int i = 0; i < 32; i += 8) {
        float v = tf[tx][ty + i];
        __nv_bfloat16 h, l; split2(v, h, l);
        Oh[(size_t)(et + ty + i) * D_ + dt + tx] = h;
        Ol[(size_t)(et + ty + i) * D_ + dt + tx] = l;
    }
}

// bf16 transpose: V [b][s][d] -> V^T [b][d][s] (hi and lo)
__global__ void __launch_bounds__(256) ca_transpose_v()
{
    __shared__ __nv_bfloat16 th[32][33], tl[32][33];
    const int dt = blockIdx.x * 32, st = blockIdx.y * 32, b = blockIdx.z;
    const int tx = threadIdx.x & 31, ty = threadIdx.x >> 5;
    const __nv_bfloat16* Sh = g_Vh + (size_t)b * S_ * D_;
    const __nv_bfloat16* Sl = g_Vl + (size_t)b * S_ * D_;
    #pragma unroll
    for (int i = 0; i < 32; i += 8) {
        th[ty + i][tx] = Sh[(size_t)(st + ty + i) * D_ + dt + tx];
        tl[ty + i][tx] = Sl[(size_t)(st + ty + i) * D_ + dt + tx];
    }
    __syncthreads();
    __nv_bfloat16* Oh = g_Vth + (size_t)b * D_ * S_;
    __nv_bfloat16* Ol = g_Vtl + (size_t)b * D_ * S_;
    #pragma unroll
    for (int i = 0; i < 32; i += 8) {
        Oh[(size_t)(dt + ty + i) * S_ + st + tx] = th[tx][ty + i];
        Ol[(size_t)(dt + ty + i) * S_ + st + tx] = tl[tx][ty + i];
    }
}

// ---------------------------------------------------------------------------
// GEMM kernel: 128x128 tile, K-chunk 64, 2-stage cp.async double buffer,
// split-bf16 3-pass mma.sync. 8 warps, 4(m) x 2(n) warp grid.
// MODE 0: Q/K/V proj (bf16 hi/lo out)  MODE 1: scores (fp32*scale out)
// MODE 2: PV (fp32 out, causal K bound)
// ---------------------------------------------------------------------------
constexpr int TILE_B  = 16384;          // 128 rows x 128B
constexpr int STAGE_B = 4 * TILE_B;     // Ah, Al, Bh, Bl
constexpr int SMEM_TOTAL = 2 * STAGE_B; // 131072

__device__ __forceinline__ void load_tile(const __nv_bfloat16* __restrict__ src,
                                          int ld, uint32_t dstbase, int tid) {
    #pragma unroll
    for (int it = 0; it < 4; it++) {
        int idx = it * 256 + tid;
        int r = idx >> 3, cb = (idx & 7) * 16;       // cb in bytes
        cp16(dstbase + swz((uint32_t)r * 128u + cb),
             src + (size_t)r * ld + (cb >> 1));
    }
}

template<int MODE>
__global__ void __launch_bounds__(256) ca_mma_kernel(float* __restrict__ Out)
{
    extern __shared__ char smem[];

    const __nv_bfloat16 *AhP, *AlP, *BhP, *BlP;
    int lda, ldb, nchunks;
    // epilogue targets
    float* Cf = nullptr; int ldc = D_; float scale = 1.0f;
    __nv_bfloat16 *Ch = nullptr, *Cl = nullptr;

    if constexpr (MODE == 0) {
        int nT = blockIdx.x, mT = blockIdx.y, z = blockIdx.z;
        AhP = g_Xh + (size_t)mT * 128 * D_;
        AlP = g_Xl + (size_t)mT * 128 * D_;                       lda = D_;
        BhP = g_Wth + (size_t)z * D_ * D_ + (size_t)nT * 128 * D_;
        BlP = g_Wtl + (size_t)z * D_ * D_ + (size_t)nT * 128 * D_; ldb = D_;
        size_t co = (size_t)mT * 128 * D_ + nT * 128;
        Ch = ((z == 0) ? g_Qh : (z == 1) ? g_Kh : g_Vh) + co;
        Cl = ((z == 0) ? g_Ql : (z == 1) ? g_Kl : g_Vl) + co;
        ldc = D_; nchunks = D_ / 64;
    } else if constexpr (MODE == 1) {
        int kt = blockIdx.x, qt = blockIdx.y, b = blockIdx.z;
        if (kt > qt) return;
        AhP = g_Qh + (size_t)b * S_ * D_ + (size_t)qt * 128 * D_;
        AlP = g_Ql + (size_t)b * S_ * D_ + (size_t)qt * 128 * D_;  lda = D_;
        BhP = g_Kh + (size_t)b * S_ * D_ + (size_t)kt * 128 * D_;
        BlP = g_Kl + (size_t)b * S_ * D_ + (size_t)kt * 128 * D_;  ldb = D_;
        Cf = g_SC + (size_t)b * S_ * S_ + (size_t)qt * 128 * S_ + kt * 128;
        ldc = S_; nchunks = D_ / 64; scale = 0.03125f;
    } else {
        int nT = blockIdx.x, qT = blockIdx.y, b = blockIdx.z;
        AhP = g_Ph + (size_t)b * S_ * S_ + (size_t)qT * 128 * S_;
        AlP = g_Pl + (size_t)b * S_ * S_ + (size_t)qT * 128 * S_;  lda = S_;
        BhP = g_Vth + (size_t)b * D_ * S_ + (size_t)nT * 128 * S_;
        BlP = g_Vtl + (size_t)b * D_ * S_ + (size_t)nT * 128 * S_; ldb = S_;
        Cf = Out + (size_t)b * S_ * D_ + (size_t)qT * 128 * D_ + nT * 128;
        ldc = D_; nchunks = (qT + 1) * 2;   // causal K bound
    }

    const uint32_t sb = smem_u32(smem);
    const int tid  = threadIdx.x;
    const int wid  = tid >> 5, lane = tid & 31;
    const int wm   = wid >> 1, wn = wid & 1;
    const int lrow  = lane & 15;
    const int lkofs = (lane >> 4) * 8;

    float acc[2][8][4] = {};

    // prologue: stage 0
    {
        uint32_t base = sb;
        load_tile(AhP, lda, base,              tid);
        load_tile(AlP, lda, base + TILE_B,     tid);
        load_tile(BhP, ldb, base + 2 * TILE_B, tid);
        load_tile(BlP, ldb, base + 3 * TILE_B, tid);
        CP_COMMIT();
    }

    for (int ch = 0; ch < nchunks; ch++) {
        const int st = ch & 1;
        if (ch + 1 < nchunks) {
            const int k0 = (ch + 1) * 64;
            uint32_t base = sb + (st ^ 1) * STAGE_B;
            load_tile(AhP + k0, lda, base,              tid);
            load_tile(AlP + k0, lda, base + TILE_B,     tid);
            load_tile(BhP + k0, ldb, base + 2 * TILE_B, tid);
            load_tile(BlP + k0, ldb, base + 3 * TILE_B, tid);
            CP_COMMIT();
            CP_WAIT(1);
        } else {
            CP_WAIT(0);
        }
        __syncthreads();

        const uint32_t sB = sb + st * STAGE_B;
        #pragma unroll
        for (int ks = 0; ks < 4; ks++) {
            const uint32_t colb = (uint32_t)(ks * 16 + lkofs) * 2u;

            uint32_t ah[2][4], al[2][4];
            #pragma unroll
            for (int mt = 0; mt < 2; mt++) {
                uint32_t sw = swz((uint32_t)(wm * 32 + mt * 16 + lrow) * 128u + colb);
                LDSM_X4(ah[mt][0], ah[mt][1], ah[mt][2], ah[mt][3], sB + sw);
                LDSM_X4(al[mt][0], al[mt][1], al[mt][2], al[mt][3], sB + TILE_B + sw);
            }
            uint32_t bb[4][4];
            #pragma unroll
            for (int nt2 = 0; nt2 < 4; nt2++) {
                uint32_t sw = swz((uint32_t)(wn * 64 + nt2 * 16 + lrow) * 128u + colb);
                LDSM_X4(bb[nt2][0], bb[nt2][1], bb[nt2][2], bb[nt2][3],
                        sB + 2 * TILE_B + sw);
            }
            #pragma unroll
            for (int mt = 0; mt < 2; mt++)
                #pragma unroll
                for (int nt = 0; nt < 8; nt++) {
                    const int nt2 = nt >> 1, pr = nt & 1;
                    MMA_BF16(acc[mt][nt], ah[mt], bb[nt2][pr], bb[nt2][pr + 2]);
                }
            #pragma unroll
            for (int mt = 0; mt < 2; mt++)
                #pragma unroll
                for (int nt = 0; nt < 8; nt++) {
                    const int nt2 = nt >> 1, pr = nt & 1;
                    MMA_BF16(acc[mt][nt], al[mt], bb[nt2][pr], bb[nt2][pr + 2]);
                }
            #pragma unroll
            for (int nt2 = 0; nt2 < 4; nt2++) {
                uint32_t sw = swz((uint32_t)(wn * 64 + nt2 * 16 + lrow) * 128u + colb);
                LDSM_X4(bb[nt2][0], bb[nt2][1], bb[nt2][2], bb[nt2][3],
                        sB + 3 * TILE_B + sw);
            }
            #pragma unroll
            for (int mt = 0; mt < 2; mt++)
                #pragma unroll
                for (int nt = 0; nt < 8; nt++) {
                    const int nt2 = nt >> 1, pr = nt & 1;
                    MMA_BF16(acc[mt][nt], ah[mt], bb[nt2][pr], bb[nt2][pr + 2]);
                }
        }
        __syncthreads();
    }

    // Epilogue
    const int erow = wm * 32 + (lane >> 2);
    const int ecol = wn * 64 + (lane & 3) * 2;
    #pragma unroll
    for (int mt = 0; mt < 2; mt++) {
        #pragma unroll
        for (int nt = 0; nt < 8; nt++) {
            const int r0 = erow + mt * 16, r1 = r0 + 8, c = ecol + nt * 8;
            if constexpr (MODE == 0) {
                __nv_bfloat16 h0, l0, h1, l1;
                split2(acc[mt][nt][0], h0, l0); split2(acc[mt][nt][1], h1, l1);
                *(__nv_bfloat162*)(Ch + (size_t)r0 * ldc + c) = __nv_bfloat162(h0, h1);
                *(__nv_bfloat162*)(Cl + (size_t)r0 * ldc + c) = __nv_bfloat162(l0, l1);
                split2(acc[mt][nt][2], h0, l0); split2(acc[mt][nt][3], h1, l1);
                *(__nv_bfloat162*)(Ch + (size_t)r1 * ldc + c) = __nv_bfloat162(h0, h1);
                *(__nv_bfloat162*)(Cl + (size_t)r1 * ldc + c) = __nv_bfloat162(l0, l1);
            } else {
                *(float2*)(Cf + (size_t)r0 * ldc + c) =
                    make_float2(acc[mt][nt][0] * scale, acc[mt][nt][1] * scale);
                *(float2*)(Cf + (size_t)r1 * ldc + c) =
                    make_float2(acc[mt][nt][2] * scale, acc[mt][nt][3] * scale);
            }
        }
    }
}

// ---------------------------------------------------------------------------
// Causal row softmax: fp32 scores -> bf16 hi/lo probs
// ---------------------------------------------------------------------------
__global__ void __launch_bounds__(256) ca_softmax_kernel()
{
    __shared__ float buf[S_];
    __shared__ float red[256];

    const int row = blockIdx.x;
    const int b   = row >> 11;
    const int q   = row & (S_ - 1);
    const float* sc = g_SC + (size_t)b * S_ * S_ + (size_t)q * S_;
    __nv_bfloat16* ph = g_Ph + (size_t)b * S_ * S_ + (size_t)q * S_;
    __nv_bfloat16* pl = g_Pl + (size_t)b * S_ * S_ + (size_t)q * S_;
    const int len = q + 1;
    const int tid = threadIdx.x;

    float m = -3.4e38f;
    for (int i = tid; i < len; i += 256) {
        float v = sc[i];
        buf[i] = v;
        m = fmaxf(m, v);
    }
    red[tid] = m;
    __syncthreads();
    #pragma unroll
    for (int s = 128; s > 0; s >>= 1) {
        if (tid < s) red[tid] = fmaxf(red[tid], red[tid + s]);
        __syncthreads();
    }
    m = red[0];
    __syncthreads();

    float sum = 0.f;
    for (int i = tid; i < len; i += 256) {
        float e = __expf(buf[i] - m);
        buf[i] = e;
        sum += e;
    }
    red[tid] = sum;
    __syncthreads();
    #pragma unroll
    for (int s = 128; s > 0; s >>= 1) {
        if (tid < s) red[tid] += red[tid + s];
        __syncthreads();
    }
    const float inv = 1.0f / red[0];

    for (int i = tid; i < len; i += 256) {
        __nv_bfloat16 h, l;
        split2(buf[i] * inv, h, l);
        ph[i] = h; pl[i] = l;
    }
    const __nv_bfloat16 z = __float2bfloat16(0.f);
    for (int i = len + tid; i < S_; i += 256) { ph[i] = z; pl[i] = z; }
}

// ---------------------------------------------------------------------------
extern "C" void kernel_launch(void* const* d_in, const int* in_sizes, int n_in,
                              void* d_out, int out_size)
{
    const float* x  = (const float*)d_in[0];
    const float* Wq = (const float*)d_in[1];
    const float* Wk = (const float*)d_in[2];
    const float* Wv = (const float*)d_in[3];
    float* out = (float*)d_out;

    cudaFuncSetAttribute(ca_mma_kernel<0>, cudaFuncAttributeMaxDynamicSharedMemorySize, SMEM_TOTAL);
    cudaFuncSetAttribute(ca_mma_kernel<1>, cudaFuncAttributeMaxDynamicSharedMemorySize, SMEM_TOTAL);
    cudaFuncSetAttribute(ca_mma_kernel<2>, cudaFuncAttributeMaxDynamicSharedMemorySize, SMEM_TOTAL);

    // 0) one-time operand conversion
    ca_split_x<<<(NR * D_ / 4 + 255) / 256, 256>>>(x);
    ca_tsplit_w<<<dim3(D_ / 32, D_ / 32, 3), 256>>>(Wq, Wk, Wv);

    // 1) QKV projections (writes Q/K/V as bf16 hi/lo)
    ca_mma_kernel<0><<<dim3(D_ / 128, NR / 128, 3), 256, SMEM_TOTAL>>>(out);

    // 1b) V -> V^T
    ca_transpose_v<<<dim3(D_ / 32, S_ / 32, B_), 256>>>();

    // 2) Scores (causal lower-tri tiles only), fp32
    ca_mma_kernel<1><<<dim3(S_ / 128, S_ / 128, B_), 256, SMEM_TOTAL>>>(out);

    // 3) Row softmax -> bf16 hi/lo probs
    ca_softmax_kernel<<<NR, 256>>>();

    // 4) O = P @ V
    ca_mma_kernel<2><<<dim3(D_ / 128, S_ / 128, B_), 256, SMEM_TOTAL>>>(out);
}

// round 8
// speedup vs baseline: 3.0288x; 1.0273x over previous
#include <cuda_runtime.h>
#include <cuda_bf16.h>
#include <cstdint>

// Problem constants
constexpr int B_  = 4;
constexpr int S_  = 2048;
constexpr int D_  = 1024;
constexpr int NR  = B_ * S_;

// ---------------------------------------------------------------------------
// Persistent bf16 hi/lo operand arrays + fp32 scores (device globals)
// ---------------------------------------------------------------------------
__device__ __nv_bfloat16 g_Xh [NR * D_];
__device__ __nv_bfloat16 g_Xl [NR * D_];
__device__ __nv_bfloat16 g_Wth[3 * D_ * D_];     // W^T, [z][e][d]
__device__ __nv_bfloat16 g_Wtl[3 * D_ * D_];
__device__ __nv_bfloat16 g_Qh [NR * D_];
__device__ __nv_bfloat16 g_Ql [NR * D_];
__device__ __nv_bfloat16 g_Kh [NR * D_];
__device__ __nv_bfloat16 g_Kl [NR * D_];
__device__ __nv_bfloat16 g_Vh [NR * D_];         // row-major [b*s][d]
__device__ __nv_bfloat16 g_Vl [NR * D_];
__device__ __nv_bfloat16 g_Vth[NR * D_];         // V^T, [b][d][s]
__device__ __nv_bfloat16 g_Vtl[NR * D_];
__device__ float         g_SC [(size_t)B_ * S_ * S_];
__device__ __nv_bfloat16 g_Ph [(size_t)B_ * S_ * S_];
__device__ __nv_bfloat16 g_Pl [(size_t)B_ * S_ * S_];

// ---------------------------------------------------------------------------
// Helpers
// ---------------------------------------------------------------------------
__device__ __forceinline__ uint32_t swz(uint32_t off) {
    return off ^ ((off >> 3) & 0x70);
}
__device__ __forceinline__ uint32_t smem_u32(const void* p) {
    uint32_t a;
    asm("{ .reg .u64 t; cvta.to.shared.u64 t, %1; cvt.u32.u64 %0, t; }" : "=r"(a) : "l"(p));
    return a;
}
__device__ __forceinline__ void split2(float v, __nv_bfloat16& h, __nv_bfloat16& l) {
    h = __float2bfloat16(v);
    l = __float2bfloat16(v - __bfloat162float(h));
}

#define LDSM_X4(r0, r1, r2, r3, addr) \
    asm volatile("ldmatrix.sync.aligned.m8n8.x4.shared.b16 {%0,%1,%2,%3}, [%4];" \
        : "=r"(r0), "=r"(r1), "=r"(r2), "=r"(r3) : "r"(addr))

#define MMA_BF16(c, a, b0, b1) \
    asm volatile("mma.sync.aligned.m16n8k16.row.col.f32.bf16.bf16.f32 " \
        "{%0,%1,%2,%3}, {%4,%5,%6,%7}, {%8,%9}, {%0,%1,%2,%3};" \
        : "+f"((c)[0]), "+f"((c)[1]), "+f"((c)[2]), "+f"((c)[3]) \
        : "r"((a)[0]), "r"((a)[1]), "r"((a)[2]), "r"((a)[3]), "r"(b0), "r"(b1))

__device__ __forceinline__ void cp16(uint32_t dst, const void* src) {
    asm volatile("cp.async.cg.shared.global [%0], [%1], 16;" :: "r"(dst), "l"(src));
}
#define CP_COMMIT() asm volatile("cp.async.commit_group;" ::: "memory")
#define CP_WAIT(n)  asm volatile("cp.async.wait_group %0;" :: "n"(n) : "memory")

// ---------------------------------------------------------------------------
// Conversion kernels (run once, memory-bound)
// ---------------------------------------------------------------------------
__global__ void __launch_bounds__(256) ca_split_x(const float* __restrict__ X)
{
    int idx = (blockIdx.x * 256 + threadIdx.x) * 4;
    if (idx >= NR * D_) return;
    float4 f = *(const float4*)(X + idx);
    __nv_bfloat16 h[4], l[4];
    split2(f.x, h[0], l[0]); split2(f.y, h[1], l[1]);
    split2(f.z, h[2], l[2]); split2(f.w, h[3], l[3]);
    *(uint2*)(g_Xh + idx) = *(uint2*)h;
    *(uint2*)(g_Xl + idx) = *(uint2*)l;
}

// W [d][e] fp32 -> W^T [e][d] bf16 hi/lo, 32x32 smem tiles
__global__ void __launch_bounds__(256) ca_tsplit_w(
    const float* __restrict__ Wq, const float* __restrict__ Wk,
    const float* __restrict__ Wv)
{
    __shared__ float tf[32][33];
    const int z = blockIdx.z;
    const float* W = (z == 0) ? Wq : (z == 1) ? Wk : Wv;
    const int dt = blockIdx.y * 32, et = blockIdx.x * 32;
    const int tx = threadIdx.x & 31, ty = threadIdx.x >> 5;   // ty 0..7
    #pragma unroll
    for (int i = 0; i < 32; i += 8)
        tf[ty + i][tx] = W[(size_t)(dt + ty + i) * D_ + et + tx];
    __syncthreads();
    __nv_bfloat16* Oh = g_Wth + (size_t)z * D_ * D_;
    __nv_bfloat16* Ol = g_Wtl + (size_t)z * D_ * D_;
    #pragma unroll
    for (int i = 0; i < 32; i += 8) {
        float v = tf[tx][ty + i];
        __nv_bfloat16 h, l; split2(v, h, l);
        Oh[(size_t)(et + ty + i) * D_ + dt + tx] = h;
        Ol[(size_t)(et + ty + i) * D_ + dt + tx] = l;
    }
}

// bf16 transpose: V [b][s][d] -> V^T [b][d][s] (hi and lo)
__global__ void __launch_bounds__(256) ca_transpose_v()
{
    __shared__ __nv_bfloat16 th[32][33], tl[32][33];
    const int dt = blockIdx.x * 32, st = blockIdx.y * 32, b = blockIdx.z;
    const int tx = threadIdx.x & 31, ty = threadIdx.x >> 5;
    const __nv_bfloat16* Sh = g_Vh + (size_t)b * S_ * D_;
    const __nv_bfloat16* Sl = g_Vl + (size_t)b * S_ * D_;
    #pragma unroll
    for (int i = 0; i < 32; i += 8) {
        th[ty + i][tx] = Sh[(size_t)(st + ty + i) * D_ + dt + tx];
        tl[ty + i][tx] = Sl[(size_t)(st + ty + i) * D_ + dt + tx];
    }
    __syncthreads();
    __nv_bfloat16* Oh = g_Vth + (size_t)b * D_ * S_;
    __nv_bfloat16* Ol = g_Vtl + (size_t)b * D_ * S_;
    #pragma unroll
    for (int i = 0; i < 32; i += 8) {
        Oh[(size_t)(dt + ty + i) * S_ + st + tx] = th[tx][ty + i];
        Ol[(size_t)(dt + ty + i) * S_ + st + tx] = tl[tx][ty + i];
    }
}

// ---------------------------------------------------------------------------
// GEMM kernel: 128x128 tile, K-chunk 64, 3-stage cp.async pipeline (one
// __syncthreads per chunk), split-bf16 3-pass mma.sync.
// 8 warps, 4(m) x 2(n) warp grid.
// MODE 0: Q/K/V proj (bf16 hi/lo out)
// MODE 1: scores (fp32*scale out, triangular 1D grid)
// MODE 2: PV (fp32 out, causal K bound, heavy-first qT order)
// ---------------------------------------------------------------------------
constexpr int TILE_B  = 16384;          // 128 rows x 128B
constexpr int STAGE_B = 4 * TILE_B;     // Ah, Al, Bh, Bl
constexpr int NSTAGE  = 3;
constexpr int SMEM_TOTAL = NSTAGE * STAGE_B;   // 196608

__device__ __forceinline__ void load_tile(const __nv_bfloat16* __restrict__ src,
                                          int ld, uint32_t dstbase, int tid) {
    #pragma unroll
    for (int it = 0; it < 4; it++) {
        int idx = it * 256 + tid;
        int r = idx >> 3, cb = (idx & 7) * 16;       // cb in bytes
        cp16(dstbase + swz((uint32_t)r * 128u + cb),
             src + (size_t)r * ld + (cb >> 1));
    }
}

template<int MODE>
__global__ void __launch_bounds__(256) ca_mma_kernel(float* __restrict__ Out)
{
    extern __shared__ char smem[];

    const __nv_bfloat16 *AhP, *AlP, *BhP, *BlP;
    int lda, ldb, nchunks;
    float* Cf = nullptr; int ldc = D_; float scale = 1.0f;
    __nv_bfloat16 *Ch = nullptr, *Cl = nullptr;

    if constexpr (MODE == 0) {
        int nT = blockIdx.x, mT = blockIdx.y, z = blockIdx.z;
        AhP = g_Xh + (size_t)mT * 128 * D_;
        AlP = g_Xl + (size_t)mT * 128 * D_;                       lda = D_;
        BhP = g_Wth + (size_t)z * D_ * D_ + (size_t)nT * 128 * D_;
        BlP = g_Wtl + (size_t)z * D_ * D_ + (size_t)nT * 128 * D_; ldb = D_;
        size_t co = (size_t)mT * 128 * D_ + nT * 128;
        Ch = ((z == 0) ? g_Qh : (z == 1) ? g_Kh : g_Vh) + co;
        Cl = ((z == 0) ? g_Ql : (z == 1) ? g_Kl : g_Vl) + co;
        ldc = D_; nchunks = D_ / 64;
    } else if constexpr (MODE == 1) {
        // triangular decode: flat index -> (qt, kt), kt <= qt
        int i = blockIdx.x, b = blockIdx.z;
        int qt = (int)((sqrtf(8.f * (float)i + 1.f) - 1.f) * 0.5f);
        while ((qt + 1) * (qt + 2) / 2 <= i) qt++;
        while (qt * (qt + 1) / 2 > i) qt--;
        int kt = i - qt * (qt + 1) / 2;
        AhP = g_Qh + (size_t)b * S_ * D_ + (size_t)qt * 128 * D_;
        AlP = g_Ql + (size_t)b * S_ * D_ + (size_t)qt * 128 * D_;  lda = D_;
        BhP = g_Kh + (size_t)b * S_ * D_ + (size_t)kt * 128 * D_;
        BlP = g_Kl + (size_t)b * S_ * D_ + (size_t)kt * 128 * D_;  ldb = D_;
        Cf = g_SC + (size_t)b * S_ * S_ + (size_t)qt * 128 * S_ + kt * 128;
        ldc = S_; nchunks = D_ / 64; scale = 0.03125f;
    } else {
        int nT = blockIdx.x, b = blockIdx.z;
        int qT = gridDim.y - 1 - blockIdx.y;    // heavy blocks first
        AhP = g_Ph + (size_t)b * S_ * S_ + (size_t)qT * 128 * S_;
        AlP = g_Pl + (size_t)b * S_ * S_ + (size_t)qT * 128 * S_;  lda = S_;
        BhP = g_Vth + (size_t)b * D_ * S_ + (size_t)nT * 128 * S_;
        BlP = g_Vtl + (size_t)b * D_ * S_ + (size_t)nT * 128 * S_; ldb = S_;
        Cf = Out + (size_t)b * S_ * D_ + (size_t)qT * 128 * D_ + nT * 128;
        ldc = D_; nchunks = (qT + 1) * 2;   // causal K bound
    }

    const uint32_t sb = smem_u32(smem);
    const int tid  = threadIdx.x;
    const int wid  = tid >> 5, lane = tid & 31;
    const int wm   = wid >> 1, wn = wid & 1;
    const int lrow  = lane & 15;
    const int lkofs = (lane >> 4) * 8;

    float acc[2][8][4] = {};

    // prologue: fill up to 2 stages
    {
        uint32_t base = sb;
        load_tile(AhP, lda, base,              tid);
        load_tile(AlP, lda, base + TILE_B,     tid);
        load_tile(BhP, ldb, base + 2 * TILE_B, tid);
        load_tile(BlP, ldb, base + 3 * TILE_B, tid);
        CP_COMMIT();
        if (nchunks > 1) {
            base = sb + STAGE_B;
            load_tile(AhP + 64, lda, base,              tid);
            load_tile(AlP + 64, lda, base + TILE_B,     tid);
            load_tile(BhP + 64, ldb, base + 2 * TILE_B, tid);
            load_tile(BlP + 64, ldb, base + 3 * TILE_B, tid);
            CP_COMMIT();
        }
    }

    int st = 0;
    for (int ch = 0; ch < nchunks; ch++) {
        // wait for chunk ch's stage, then one barrier (data visibility +
        // all warps done reading the stage we're about to overwrite)
        if (ch + 1 < nchunks) { CP_WAIT(1); } else { CP_WAIT(0); }
        __syncthreads();

        if (ch + 2 < nchunks) {
            const int k0 = (ch + 2) * 64;
            int st2 = st + 2; if (st2 >= NSTAGE) st2 -= NSTAGE;
            uint32_t base = sb + st2 * STAGE_B;
            load_tile(AhP + k0, lda, base,              tid);
            load_tile(AlP + k0, lda, base + TILE_B,     tid);
            load_tile(BhP + k0, ldb, base + 2 * TILE_B, tid);
            load_tile(BlP + k0, ldb, base + 3 * TILE_B, tid);
            CP_COMMIT();
        }

        const uint32_t sB = sb + st * STAGE_B;
        #pragma unroll
        for (int ks = 0; ks < 4; ks++) {
            const uint32_t colb = (uint32_t)(ks * 16 + lkofs) * 2u;

            uint32_t ah[2][4], al[2][4];
            #pragma unroll
            for (int mt = 0; mt < 2; mt++) {
                uint32_t sw = swz((uint32_t)(wm * 32 + mt * 16 + lrow) * 128u + colb);
                LDSM_X4(ah[mt][0], ah[mt][1], ah[mt][2], ah[mt][3], sB + sw);
                LDSM_X4(al[mt][0], al[mt][1], al[mt][2], al[mt][3], sB + TILE_B + sw);
            }
            uint32_t bb[4][4];
            #pragma unroll
            for (int nt2 = 0; nt2 < 4; nt2++) {
                uint32_t sw = swz((uint32_t)(wn * 64 + nt2 * 16 + lrow) * 128u + colb);
                LDSM_X4(bb[nt2][0], bb[nt2][1], bb[nt2][2], bb[nt2][3],
                        sB + 2 * TILE_B + sw);
            }
            #pragma unroll
            for (int mt = 0; mt < 2; mt++)
                #pragma unroll
                for (int nt = 0; nt < 8; nt++) {
                    const int nt2 = nt >> 1, pr = nt & 1;
                    MMA_BF16(acc[mt][nt], ah[mt], bb[nt2][pr], bb[nt2][pr + 2]);
                }
            #pragma unroll
            for (int mt = 0; mt < 2; mt++)
                #pragma unroll
                for (int nt = 0; nt < 8; nt++) {
                    const int nt2 = nt >> 1, pr = nt & 1;
                    MMA_BF16(acc[mt][nt], al[mt], bb[nt2][pr], bb[nt2][pr + 2]);
                }
            #pragma unroll
            for (int nt2 = 0; nt2 < 4; nt2++) {
                uint32_t sw = swz((uint32_t)(wn * 64 + nt2 * 16 + lrow) * 128u + colb);
                LDSM_X4(bb[nt2][0], bb[nt2][1], bb[nt2][2], bb[nt2][3],
                        sB + 3 * TILE_B + sw);
            }
            #pragma unroll
            for (int mt = 0; mt < 2; mt++)
                #pragma unroll
                for (int nt = 0; nt < 8; nt++) {
                    const int nt2 = nt >> 1, pr = nt & 1;
                    MMA_BF16(acc[mt][nt], ah[mt], bb[nt2][pr], bb[nt2][pr + 2]);
                }
        }
        if (++st == NSTAGE) st = 0;
    }

    // Epilogue
    const int erow = wm * 32 + (lane >> 2);
    const int ecol = wn * 64 + (lane & 3) * 2;
    #pragma unroll
    for (int mt = 0; mt < 2; mt++) {
        #pragma unroll
        for (int nt = 0; nt < 8; nt++) {
            const int r0 = erow + mt * 16, r1 = r0 + 8, c = ecol + nt * 8;
            if constexpr (MODE == 0) {
                __nv_bfloat16 h0, l0, h1, l1;
                split2(acc[mt][nt][0], h0, l0); split2(acc[mt][nt][1], h1, l1);
                *(__nv_bfloat162*)(Ch + (size_t)r0 * ldc + c) = __nv_bfloat162(h0, h1);
                *(__nv_bfloat162*)(Cl + (size_t)r0 * ldc + c) = __nv_bfloat162(l0, l1);
                split2(acc[mt][nt][2], h0, l0); split2(acc[mt][nt][3], h1, l1);
                *(__nv_bfloat162*)(Ch + (size_t)r1 * ldc + c) = __nv_bfloat162(h0, h1);
                *(__nv_bfloat162*)(Cl + (size_t)r1 * ldc + c) = __nv_bfloat162(l0, l1);
            } else {
                *(float2*)(Cf + (size_t)r0 * ldc + c) =
                    make_float2(acc[mt][nt][0] * scale, acc[mt][nt][1] * scale);
                *(float2*)(Cf + (size_t)r1 * ldc + c) =
                    make_float2(acc[mt][nt][2] * scale, acc[mt][nt][3] * scale);
            }
        }
    }
}

// ---------------------------------------------------------------------------
// Causal row softmax: fp32 scores -> bf16 hi/lo probs
// ---------------------------------------------------------------------------
__global__ void __launch_bounds__(256) ca_softmax_kernel()
{
    __shared__ float buf[S_];
    __shared__ float red[256];

    const int row = blockIdx.x;
    const int b   = row >> 11;
    const int q   = row & (S_ - 1);
    const float* sc = g_SC + (size_t)b * S_ * S_ + (size_t)q * S_;
    __nv_bfloat16* ph = g_Ph + (size_t)b * S_ * S_ + (size_t)q * S_;
    __nv_bfloat16* pl = g_Pl + (size_t)b * S_ * S_ + (size_t)q * S_;
    const int len = q + 1;
    const int tid = threadIdx.x;

    float m = -3.4e38f;
    for (int i = tid; i < len; i += 256) {
        float v = sc[i];
        buf[i] = v;
        m = fmaxf(m, v);
    }
    red[tid] = m;
    __syncthreads();
    #pragma unroll
    for (int s = 128; s > 0; s >>= 1) {
        if (tid < s) red[tid] = fmaxf(red[tid], red[tid + s]);
        __syncthreads();
    }
    m = red[0];
    __syncthreads();

    float sum = 0.f;
    for (int i = tid; i < len; i += 256) {
        float e = __expf(buf[i] - m);
        buf[i] = e;
        sum += e;
    }
    red[tid] = sum;
    __syncthreads();
    #pragma unroll
    for (int s = 128; s > 0; s >>= 1) {
        if (tid < s) red[tid] += red[tid + s];
        __syncthreads();
    }
    const float inv = 1.0f / red[0];

    for (int i = tid; i < len; i += 256) {
        __nv_bfloat16 h, l;
        split2(buf[i] * inv, h, l);
        ph[i] = h; pl[i] = l;
    }
    const __nv_bfloat16 z = __float2bfloat16(0.f);
    for (int i = len + tid; i < S_; i += 256) { ph[i] = z; pl[i] = z; }
}

// ---------------------------------------------------------------------------
extern "C" void kernel_launch(void* const* d_in, const int* in_sizes, int n_in,
                              void* d_out, int out_size)
{
    const float* x  = (const float*)d_in[0];
    const float* Wq = (const float*)d_in[1];
    const float* Wk = (const float*)d_in[2];
    const float* Wv = (const float*)d_in[3];
    float* out = (float*)d_out;

    cudaFuncSetAttribute(ca_mma_kernel<0>, cudaFuncAttributeMaxDynamicSharedMemorySize, SMEM_TOTAL);
    cudaFuncSetAttribute(ca_mma_kernel<1>, cudaFuncAttributeMaxDynamicSharedMemorySize, SMEM_TOTAL);
    cudaFuncSetAttribute(ca_mma_kernel<2>, cudaFuncAttributeMaxDynamicSharedMemorySize, SMEM_TOTAL);

    // 0) one-time operand conversion
    ca_split_x<<<(NR * D_ / 4 + 255) / 256, 256>>>(x);
    ca_tsplit_w<<<dim3(D_ / 32, D_ / 32, 3), 256>>>(Wq, Wk, Wv);

    // 1) QKV projections (writes Q/K/V as bf16 hi/lo)
    ca_mma_kernel<0><<<dim3(D_ / 128, NR / 128, 3), 256, SMEM_TOTAL>>>(out);

    // 1b) V -> V^T
    ca_transpose_v<<<dim3(D_ / 32, S_ / 32, B_), 256>>>();

    // 2) Scores: triangular grid, 136 live tiles per batch
    constexpr int NTRI = (S_ / 128) * (S_ / 128 + 1) / 2;   // 136
    ca_mma_kernel<1><<<dim3(NTRI, 1, B_), 256, SMEM_TOTAL>>>(out);

    // 3) Row softmax -> bf16 hi/lo probs
    ca_softmax_kernel<<<NR, 256>>>();

    // 4) O = P @ V (heavy qT first)
    ca_mma_kernel<2><<<dim3(D_ / 128, S_ / 128, B_), 256, SMEM_TOTAL>>>(out);
}